// round 16
// baseline (speedup 1.0000x reference)
#include <cuda_runtime.h>
#include <cstdint>
#include <cstddef>

// ---------------------------------------------------------------------------
// NonLocalBlock: B=16, C=64, H=W=64, C1=8, C2=32
// out = gamma * conv1x1(attn_out, w_last, b_last) + x
// Attention v5: tf32 mma QK + PV, register exp, paired-float2 smem layouts
// (LDS.64/STS.64 everywhere in the hot loop), 512 threads / 16 warps.
// ---------------------------------------------------------------------------

#define DINL __device__ __forceinline__

DINL unsigned long long pk2(float lo, float hi) {
    unsigned long long r;
    asm("mov.b64 %0, {%1, %2};" : "=l"(r) : "f"(lo), "f"(hi));
    return r;
}
DINL void upk2(unsigned long long v, float& lo, float& hi) {
    asm("mov.b64 {%0, %1}, %2;" : "=f"(lo), "=f"(hi) : "l"(v));
}
DINL unsigned long long fma2(unsigned long long a, unsigned long long b, unsigned long long c) {
    unsigned long long d;
    asm("fma.rn.f32x2 %0, %1, %2, %3;" : "=l"(d) : "l"(a), "l"(b), "l"(c));
    return d;
}
DINL unsigned long long mul2(unsigned long long a, unsigned long long b) {
    unsigned long long d;
    asm("mul.rn.f32x2 %0, %1, %2;" : "=l"(d) : "l"(a), "l"(b));
    return d;
}
DINL float ex2(float x) {
    float r;
    asm("ex2.approx.f32 %0, %1;" : "=f"(r) : "f"(x));
    return r;
}
DINL uint32_t f2tf32(float v) {
    uint32_t u;
    asm("cvt.rna.tf32.f32 %0, %1;" : "=r"(u) : "f"(v));
    return u;
}

// m16n8k8 tf32 mma: C(f32) += A(tf32) * B(tf32)
#define MMA_TF32(c, a0, a1, a2, a3, b0, b1)                                   \
    asm volatile(                                                             \
        "mma.sync.aligned.m16n8k8.row.col.f32.tf32.tf32.f32 "                 \
        "{%0,%1,%2,%3}, {%4,%5,%6,%7}, {%8,%9}, {%0,%1,%2,%3};"               \
        : "+f"((c)[0]), "+f"((c)[1]), "+f"((c)[2]), "+f"((c)[3])              \
        : "r"(a0), "r"(a1), "r"(a2), "r"(a3), "r"(b0), "r"(b1))

// scratch (no allocation allowed -> __device__ globals)
__device__ float g_delta[16 * 4096 * 8];   // [b][n][8]
__device__ float g_phiP [16 * 8 * 1024];   // [b][c1][1024]
__device__ float g_gP   [16 * 1024 * 32];  // [b][m][32]

// ---------------------------------------------------------------------------
// Kernel 1: fused 3x conv1x1 (48 out ch) + 2x2 maxpool for phi/g.
// One thread per PIXEL (sub-pixel of a pooled site); 4 lanes per site merge
// pooling via 2x shfl_xor. grid (8,16), 512 threads -> 128 CTAs, 16 warps/SM.
// ---------------------------------------------------------------------------
__global__ __launch_bounds__(512, 1) void conv_pool_kernel(
    const float* __restrict__ x,
    const float* __restrict__ w_delta, const float* __restrict__ b_delta,
    const float* __restrict__ w_phi,   const float* __restrict__ b_phi,
    const float* __restrict__ w_g,     const float* __restrict__ b_g)
{
    __shared__ ulonglong2 ws[64][12];   // [c][pair of 48 outputs]
    __shared__ float bias[48];
    const int tid = threadIdx.x;

    for (int i = tid; i < 3072; i += 512) {
        int c = i / 48, o = i - c * 48;
        float w;
        if (o < 8)       w = w_delta[o * 64 + c];
        else if (o < 16) w = w_phi[(o - 8) * 64 + c];
        else             w = w_g[(o - 16) * 64 + c];
        ((float*)&ws[c][0])[o] = w;
    }
    if (tid < 48)
        bias[tid] = (tid < 8) ? b_delta[tid] : (tid < 16) ? b_phi[tid - 8] : b_g[tid - 16];
    __syncthreads();

    const int b    = blockIdx.y;
    const int t    = blockIdx.x * 512 + tid;   // 0..4095 pixel-slot
    const int site = t >> 2;                   // pooled site 0..1023
    const int sub  = t & 3;                    // 0..3 within 2x2 window
    const int sy   = site >> 5, sx = site & 31;
    const int row  = 2 * sy + (sub >> 1);
    const int col  = 2 * sx + (sub & 1);

    const float* xp = x + (size_t)b * 262144 + row * 64 + col;

    unsigned long long a[24];
#pragma unroll
    for (int k = 0; k < 24; k++) a[k] = 0ull;

#pragma unroll 4
    for (int c = 0; c < 64; c++) {
        float xv = xp[c * 4096];
        unsigned long long xx = pk2(xv, xv);
#pragma unroll
        for (int k = 0; k < 12; k++) {
            ulonglong2 w = ws[c][k];           // broadcast LDS.128
            a[2*k]   = fma2(w.x, xx, a[2*k]);
            a[2*k+1] = fma2(w.y, xx, a[2*k+1]);
        }
    }

    float f[48];
#pragma unroll
    for (int k = 0; k < 24; k++) upk2(a[k], f[2*k], f[2*k+1]);

    // delta for this pixel
    float* dp = g_delta + ((size_t)(b * 4096 + row * 64 + col)) * 8;
#pragma unroll
    for (int j = 0; j < 8; j++) dp[j] = f[j] + bias[j];

    // 2x2 pooling across the 4 sub-lanes (butterfly -> all lanes have max)
    float pm[40];
#pragma unroll
    for (int j = 0; j < 40; j++) {
        float v = f[8 + j];
        v = fmaxf(v, __shfl_xor_sync(0xffffffffu, v, 1));
        v = fmaxf(v, __shfl_xor_sync(0xffffffffu, v, 2));
        pm[j] = v;
    }
    // bias commutes with max. Each sub-lane writes g channels [sub*8, sub*8+8);
    // sub 0 also writes phi.
    float* gp = g_gP + ((size_t)(b * 1024 + site)) * 32;
#pragma unroll
    for (int j = 0; j < 8; j++)
        gp[sub * 8 + j] = pm[8 + sub * 8 + j] + bias[16 + sub * 8 + j];
    if (sub == 0) {
#pragma unroll
        for (int j = 0; j < 8; j++)
            g_phiP[(b * 8 + j) * 1024 + site] = pm[j] + bias[8 + j];
    }
}

// ---------------------------------------------------------------------------
// Kernel 2: attention (tf32 mma QK + PV) + fused conv + residual.
// grid (8,16): 512 queries/CTA, 512 threads (16 warps); warp wid owns query
// m-tiles wid*2, wid*2+1.
// Paired layouts (pairs adjacent for LDS.64):
//   Vp[c][perm(m)]  pitch 1032 : pair (k, k+4) within each 8-octet
//   Kp[m][perm(c)]  pitch 8    : pair (c, c+4)
//   Pw[k][q-pairs]  pitch 40   : pair (q, q+8) within each 16-tile
// smem (floats):
//   Vp  @ 0      (33024)   Kp @ 33024 (8192)   Pw @ 41216 (10240 = 16*640)
//   wls @ 51456 (2048)     bls @ 53504 (64)    lS @ 53568 (512)
// total 54080 floats = 216320 B. Osm (512x33) reuses Vp region in epilogue.
// ---------------------------------------------------------------------------
static constexpr int SM_FLOATS = 54080;

__global__ __launch_bounds__(512, 1) void attn_kernel(
    const float* __restrict__ x,
    const float* __restrict__ w_last, const float* __restrict__ b_last,
    const float* __restrict__ gamma,  float* __restrict__ out)
{
    extern __shared__ float sm[];
    uint32_t* Vp  = (uint32_t*)sm;              // [32][1032]
    uint32_t* Kp  = (uint32_t*)(sm + 33024);    // [1024][8]
    float*    wls = sm + 51456;
    float*    bls = sm + 53504;
    float*    lS  = sm + 53568;

    const int tid  = threadIdx.x;
    const int wid  = tid >> 5;
    const int lane = tid & 31;
    const int g    = lane >> 2;         // 0..7
    const int t    = lane & 3;          // 0..3
    const int b    = blockIdx.y;

    float* Pw = sm + 41216 + wid * 640;         // per-warp [16][40]

    // V fill (transposed, tf32, pair-permuted): pos(m) within 8: 2*(m&3) | (m>>2)&1
    for (int m = tid; m < 1024; m += 512) {
        const int mp = (m & ~7) | (((m & 3) << 1) | ((m >> 2) & 1));
        const float4* gv = (const float4*)(g_gP + ((size_t)(b * 1024 + m)) * 32);
        float4 v4[8];
#pragma unroll
        for (int k = 0; k < 8; k++) v4[k] = gv[k];
        const float* vf = (const float*)v4;
#pragma unroll
        for (int c = 0; c < 32; c++) Vp[c * 1032 + mp] = f2tf32(vf[c]);
    }
    // K fill (tf32, batch-mix gather, pair-permuted over c)
#pragma unroll
    for (int j = 0; j < 8; j++) {
        int idx = b * 8 + j;
        const int cp = ((j & 3) << 1) | (j >> 2);
        const float* src = g_phiP + (size_t)((idx & 15) * 8 + (idx >> 4)) * 1024;
        for (int m = tid; m < 1024; m += 512) Kp[m * 8 + cp] = f2tf32(src[m]);
    }
    for (int i = tid; i < 2048; i += 512) wls[i] = w_last[i];
    if (tid < 64) bls[tid] = b_last[tid];
    __syncthreads();

    // Q A-frags (log2e folded, tf32)
    const float L2E = 1.4426950408889634f;
    const int qbase = blockIdx.x * 512;
    uint32_t qf[2][4];
#pragma unroll
    for (int i = 0; i < 2; i++) {
        const float* d0 = g_delta + ((size_t)b * 4096 + qbase + (wid * 2 + i) * 16 + g) * 8;
        const float* d1 = d0 + 8 * 8;   // +8 rows
        qf[i][0] = f2tf32(L2E * d0[t]);
        qf[i][1] = f2tf32(L2E * d1[t]);
        qf[i][2] = f2tf32(L2E * d0[t + 4]);
        qf[i][3] = f2tf32(L2E * d1[t + 4]);
    }

    float acc[2][16];                   // PV C-frags
    float lp[2][2];                     // l partials
#pragma unroll
    for (int i = 0; i < 2; i++) {
#pragma unroll
        for (int k = 0; k < 16; k++) acc[i][k] = 0.f;
        lp[i][0] = 0.f; lp[i][1] = 0.f;
    }

    const uint2*  Kp2 = (const uint2*)Kp;
    const uint2*  Vp2 = (const uint2*)Vp;
    float2*       Pw2 = (float2*)Pw;

    for (int ci = 0; ci < 64; ci++) {
        const int m0 = ci << 4;

        // K B-frags: one LDS.64 per n-tile ({c=t, c=t+4} pair)
        uint32_t kb0[2], kb1[2];
#pragma unroll
        for (int nt = 0; nt < 2; nt++) {
            uint2 kk = Kp2[(m0 + nt * 8 + g) * 4 + t];
            kb0[nt] = kk.x;
            kb1[nt] = kk.y;
        }

        __syncwarp();   // prev chunk's P reads complete before overwrite

        // ---- QK mma -> exp (regs) -> paired STS.64 into Pw ----
#pragma unroll
        for (int i = 0; i < 2; i++) {
#pragma unroll
            for (int nt = 0; nt < 2; nt++) {
                float c4[4] = {0.f, 0.f, 0.f, 0.f};
                MMA_TF32(c4, qf[i][0], qf[i][1], qf[i][2], qf[i][3], kb0[nt], kb1[nt]);
                float e0 = ex2(c4[0]), e1 = ex2(c4[1]);
                float e2 = ex2(c4[2]), e3 = ex2(c4[3]);
                lp[i][0] += e0 + e1;
                lp[i][1] += e2 + e3;
                // rows k = nt*8+2t (e0,e2) and nt*8+2t+1 (e1,e3); col pair (q=g, q=g+8)
                float2 w0; w0.x = e0; w0.y = e2;
                float2 w1; w1.x = e1; w1.y = e3;
                Pw2[(nt * 8 + 2 * t) * 20 + i * 8 + g]     = w0;
                Pw2[(nt * 8 + 2 * t + 1) * 20 + i * 8 + g] = w1;
            }
        }
        __syncwarp();

        // ---- PV mma: A-frags via LDS.64 pairs, V B-frags via LDS.64 pairs ----
#pragma unroll
        for (int ks = 0; ks < 2; ks++) {
            const int kb = ks * 8;
            uint32_t bf[4][2];
#pragma unroll
            for (int nt = 0; nt < 4; nt++) {
                uint2 vv = Vp2[(nt * 8 + g) * 516 + (m0 >> 1) + ks * 4 + t];
                bf[nt][0] = vv.x;       // k = kb+t
                bf[nt][1] = vv.y;       // k = kb+t+4
            }
#pragma unroll
            for (int i = 0; i < 2; i++) {
                float2 p01 = Pw2[(kb + t) * 20 + i * 8 + g];       // {a0(q=g), a1(q=g+8)}
                float2 p23 = Pw2[(kb + t + 4) * 20 + i * 8 + g];   // {a2, a3}
                uint32_t a0 = __float_as_uint(p01.x);
                uint32_t a1 = __float_as_uint(p01.y);
                uint32_t a2 = __float_as_uint(p23.x);
                uint32_t a3 = __float_as_uint(p23.y);
                MMA_TF32(acc[i] + 0,  a0, a1, a2, a3, bf[0][0], bf[0][1]);
                MMA_TF32(acc[i] + 4,  a0, a1, a2, a3, bf[1][0], bf[1][1]);
                MMA_TF32(acc[i] + 8,  a0, a1, a2, a3, bf[2][0], bf[2][1]);
                MMA_TF32(acc[i] + 12, a0, a1, a2, a3, bf[3][0], bf[3][1]);
            }
        }
    }

    // ---- l reduction across the 4 t-lanes of each g-group ----
#pragma unroll
    for (int i = 0; i < 2; i++) {
        float l0 = lp[i][0], l1 = lp[i][1];
        l0 += __shfl_xor_sync(0xffffffffu, l0, 1);
        l0 += __shfl_xor_sync(0xffffffffu, l0, 2);
        l1 += __shfl_xor_sync(0xffffffffu, l1, 1);
        l1 += __shfl_xor_sync(0xffffffffu, l1, 2);
        if (t == 0) {
            lS[(wid * 2 + i) * 16 + g]     = l0;
            lS[(wid * 2 + i) * 16 + g + 8] = l1;
        }
    }
    __syncthreads();    // all warps done with Vp before Osm overwrites it

    // ---- scatter O c-frags to smem (over Vp region): Osm[q][33] ----
    float* Osm = sm;
#pragma unroll
    for (int i = 0; i < 2; i++) {
        const int qbse = (wid * 2 + i) * 16;
#pragma unroll
        for (int nt = 0; nt < 4; nt++) {
            const int cb = nt * 8 + 2 * t;
            Osm[(qbse + g)     * 33 + cb]     = acc[i][nt * 4 + 0];
            Osm[(qbse + g)     * 33 + cb + 1] = acc[i][nt * 4 + 1];
            Osm[(qbse + g + 8) * 33 + cb]     = acc[i][nt * 4 + 2];
            Osm[(qbse + g + 8) * 33 + cb + 1] = acc[i][nt * 4 + 3];
        }
    }
    __syncthreads();

    // ---- fused epilogue (proven math): 1 query per thread ----
    unsigned long long au[16];
    {
        const float* o0 = Osm + tid * 33;
#pragma unroll
        for (int k = 0; k < 16; k++) au[k] = pk2(o0[2 * k], o0[2 * k + 1]);
    }
    const int qg = qbase + tid;
    const float gm = gamma[0];
    const float gi = __fdividef(gm, lS[tid]);
    const float* xb = x   + (size_t)b * 262144;
    float*       ob = out + (size_t)b * 262144;
    const ulonglong2* wl2 = (const ulonglong2*)wls;

    for (int c = 0; c < 64; c++) {
        const ulonglong2* wr = wl2 + c * 8;
        ulonglong2 w0 = wr[0];
        unsigned long long s0 = mul2(au[0], w0.x);
        s0 = fma2(au[1], w0.y, s0);
#pragma unroll
        for (int k = 1; k < 8; k++) {
            ulonglong2 w = wr[k];
            s0 = fma2(au[2*k],   w.x, s0);
            s0 = fma2(au[2*k+1], w.y, s0);
        }
        float ra, rb;
        upk2(s0, ra, rb);
        ob[c * 4096 + qg] = fmaf(gi, ra + rb, fmaf(gm, bls[c], xb[c * 4096 + qg]));
    }
}

// ---------------------------------------------------------------------------
extern "C" void kernel_launch(void* const* d_in, const int* in_sizes, int n_in,
                              void* d_out, int out_size)
{
    const float* x  = (const float*)d_in[0];
    const float* wd = (const float*)d_in[1];
    const float* bd = (const float*)d_in[2];
    const float* wp = (const float*)d_in[3];
    const float* bp = (const float*)d_in[4];
    const float* wg = (const float*)d_in[5];
    const float* bg = (const float*)d_in[6];
    const float* wl = (const float*)d_in[7];
    const float* bl = (const float*)d_in[8];
    const float* gm = (const float*)d_in[9];

    conv_pool_kernel<<<dim3(8, 16), 512>>>(x, wd, bd, wp, bp, wg, bg);

    const int shm = SM_FLOATS * 4;   // 216320 B
    cudaFuncSetAttribute(attn_kernel, cudaFuncAttributeMaxDynamicSharedMemorySize, shm);
    attn_kernel<<<dim3(8, 16), 512, shm>>>(x, wl, bl, gm, (float*)d_out);
}